// round 4
// baseline (speedup 1.0000x reference)
#include <cuda_runtime.h>
#include <stdint.h>

#define SLEN  400000
#define WIN   400
#define NW    1000      // SLEN / WIN
#define NA    3
#define NR    64
#define NB    2
#define KTOP  8
#define NF4   100       // WIN / 4
#define ROWF4 (SLEN / 4)
#define NTILES (NA * NW) // 3000
#define GRID  592        // 148 SMs * 4 CTAs
#define NT_MAX 6         // ceil(3000/592)

__device__ __forceinline__ unsigned long long mk_key(float v, int r) {
    unsigned u = __float_as_uint(v);
    u = (u & 0x80000000u) ? ~u : (u | 0x80000000u);   // order-preserving map
    return (((unsigned long long)u) << 6) | (unsigned long long)(63 - r);
}

__global__ __launch_bounds__(256, 4)
void fused_windowed_topk(const float* __restrict__ mixed,
                         const float* __restrict__ ref,
                         const float* __restrict__ weights,
                         float* __restrict__ out,
                         int out_size) {
    __shared__ float4 s_m[NT_MAX][NB][NF4];   // 19200 B
    __shared__ float  s_sc[NT_MAX][NB][NR];   //  3072 B

    const int tid  = threadIdx.x;
    const int warp = tid >> 5;
    const int lane = tid & 31;
    const int bid  = blockIdx.x;

    const int cnt = (NTILES - bid + GRID - 1) / GRID;   // 5 or 6 tiles

    // ---- Phase 0: stage mixed windows for all my tiles ----
    for (int v = tid; v < cnt * NB * NF4; v += 256) {
        const int i   = v / (NB * NF4);
        const int rem = v % (NB * NF4);
        const int b   = rem / NF4;
        const int j   = rem % NF4;
        const int w   = (bid + i * GRID) / NA;
        s_m[i][b][j] = __ldg((const float4*)(mixed + (size_t)b * SLEN + w * WIN) + j);
    }
    __syncthreads();

    // ---- Phase 1: stream all ref rows for all tiles, no syncs ----
    for (int i = 0; i < cnt; i++) {
        const int tile = bid + i * GRID;
        const int a = tile % NA;
        const int w = tile / NA;

        const float4* rp =
            (const float4*)(ref + ((size_t)a * NR + warp * 8) * SLEN + (size_t)w * WIN);
        float s0[8], s1[8];
#pragma unroll
        for (int rr = 0; rr < 8; rr++) { s0[rr] = 0.f; s1[rr] = 0.f; }

#pragma unroll
        for (int rb = 0; rb < 8; rb += 4) {
#pragma unroll
            for (int t = 0; t < 3; t++) {
                const int j4 = lane + 32 * t;
                float4 rv[4];
#pragma unroll
                for (int q = 0; q < 4; q++)
                    rv[q] = __ldg(rp + (rb + q) * ROWF4 + j4);
                const float4 m0 = s_m[i][0][j4];
                const float4 m1 = s_m[i][1][j4];
#pragma unroll
                for (int q = 0; q < 4; q++) {
                    s0[rb+q] += rv[q].x * m0.x + rv[q].y * m0.y + rv[q].z * m0.z + rv[q].w * m0.w;
                    s1[rb+q] += rv[q].x * m1.x + rv[q].y * m1.y + rv[q].z * m1.z + rv[q].w * m1.w;
                }
            }
            // tail: float4 96..99 on lanes 0..3 (same per-lane order as before)
            if (lane < 4) {
                const int j4 = 96 + lane;
                const float4 m0 = s_m[i][0][j4];
                const float4 m1 = s_m[i][1][j4];
#pragma unroll
                for (int q = 0; q < 4; q++) {
                    float4 rv = __ldg(rp + (rb + q) * ROWF4 + j4);
                    s0[rb+q] += rv.x * m0.x + rv.y * m0.y + rv.z * m0.z + rv.w * m0.w;
                    s1[rb+q] += rv.x * m1.x + rv.y * m1.y + rv.z * m1.z + rv.w * m1.w;
                }
            }
        }

        // ---- multi-value butterfly reduce: 16 sums in 16 shuffles ----
        // Combines the same lane-pairs in the same own+partner order as the
        // old per-sum xor tree -> bit-identical results.
        float f[16];
#pragma unroll
        for (int rr = 0; rr < 8; rr++) { f[2*rr] = s0[rr]; f[2*rr+1] = s1[rr]; }
#pragma unroll
        for (int off = 16; off >= 2; off >>= 1) {
#pragma unroll
            for (int j = 0; j < 16; j++) {          // only j < off/2 active
                if (j < (off >> 1)) {
                    float A = f[j], B = f[j + (off >> 1)];
                    float send = (lane & off) ? A : B;
                    float recv = __shfl_xor_sync(0xffffffffu, send, off);
                    f[j] = ((lane & off) ? B : A) + recv;
                }
            }
        }
        f[0] += __shfl_xor_sync(0xffffffffu, f[0], 1);
        if ((lane & 1) == 0) {
            const int k  = (lane >> 1) & 15;   // sum index held by this lane
            const int rr = k >> 1;
            const int bb = k & 1;
            s_sc[i][bb][warp * 8 + rr] = f[0] * (1.0f / WIN);
        }
    }
    __syncthreads();

    // ---- Phase 2: top-k tasks (cnt*NB <= 12) spread over all 8 warps ----
    const bool write_idx = (out_size >= NB * NA * NW * (1 + KTOP));

    for (int task = warp; task < cnt * NB; task += 8) {
        const int i = task >> 1;
        const int b = task & 1;
        const int tile = bid + i * GRID;
        const int a = tile % NA;
        const int w = tile / NA;

        unsigned long long k0 = mk_key(s_sc[i][b][lane], lane);
        unsigned long long k1 = mk_key(s_sc[i][b][lane + 32], lane + 32);

        const int base = (b * NA + a) * NW + w;
        float acc = 0.f;
#pragma unroll
        for (int k = 0; k < KTOP; k++) {
            unsigned long long km = (k0 > k1) ? k0 : k1;
#pragma unroll
            for (int o = 16; o; o >>= 1) {
                unsigned long long other = __shfl_xor_sync(0xffffffffu, km, o);
                if (other > km) km = other;
            }
            const int rsel = 63 - (int)(km & 63ull);
            acc += s_sc[i][b][rsel] * __ldg(weights + k);
            if (rsel < 32) {
                if (lane == rsel) k0 = 0ull;
            } else {
                if (lane == rsel - 32) k1 = 0ull;
            }
            if (lane == 0 && write_idx) {
                out[NB * NA * NW + base * KTOP + k] = (float)rsel;
            }
        }
        if (lane == 0) out[base] = acc;
    }
}

extern "C" void kernel_launch(void* const* d_in, const int* in_sizes, int n_in,
                              void* d_out, int out_size) {
    const float* mixed   = (const float*)d_in[0];   // [2, 400000]
    const float* ref     = (const float*)d_in[1];   // [3, 64, 400000]
    const float* weights = (const float*)d_in[2];   // [8, 1]
    float* out = (float*)d_out;

    fused_windowed_topk<<<GRID, 256>>>(mixed, ref, weights, out, out_size);
}